// round 9
// baseline (speedup 1.0000x reference)
#include <cuda_runtime.h>
#include <cuda_bf16.h>
#include <cstdint>

#define PP 32      // num networks
#define HH 128     // hidden
#define BB 32      // batch
#define TT 256     // seq len
#define CHUNK 4    // CTAs per network (cluster size)
#define NTHREADS 256
#define KTILES 10  // K = 160 = 10 x 16

// B buffer: 32 n-rows x PADW2 8-byte elements; element w = {hi word, lo word}
// of k-pair w. Row stride 704 B (== 64 mod 128 -> conflict-free LDS.128).
#define PADW2 88
#define ROWB  (PADW2 * 8)               // 704
#define BBYTES (32 * ROWB)              // 22528 per buffer

// smem byte offsets
#define OFF_BIAS 0                       // 4*32 f32
#define OFF_WOUT 512                     // 32 f32
#define OFF_B0   1024                    // 2 buffers, interleaved hi/lo
#define OFF_S    (1024 + 2 * BBYTES)     // D staging: [4 g][32 jl][34 b] f32
#define S_PAD    34
#define SMEM_BYTES (OFF_S + 4 * 32 * S_PAD * 4)   // 63488

// packed X scratch: [b][t][16 elements] = {hi word, lo word} per k-pair
__device__ uint2 Xp_g[BB * TT * 16];

__device__ __forceinline__ float tanha(float x) {
    float y; asm("tanh.approx.f32 %0, %1;" : "=f"(y) : "f"(x)); return y;
}
__device__ __forceinline__ float sigf(float x) {
    return fmaf(0.5f, tanha(0.5f * x), 0.5f);
}

__device__ __forceinline__ uint32_t pack_bf2(float lo_k, float hi_k) {
    unsigned short a = __bfloat16_as_ushort(__float2bfloat16(lo_k));
    unsigned short b = __bfloat16_as_ushort(__float2bfloat16(hi_k));
    return (uint32_t)a | ((uint32_t)b << 16);
}

__device__ __forceinline__ void mma16816(float* d, const uint32_t* a, uint32_t b0, uint32_t b1) {
    asm volatile(
        "mma.sync.aligned.m16n8k16.row.col.f32.bf16.bf16.f32 "
        "{%0,%1,%2,%3}, {%4,%5,%6,%7}, {%8,%9}, {%0,%1,%2,%3};"
        : "+f"(d[0]), "+f"(d[1]), "+f"(d[2]), "+f"(d[3])
        : "r"(a[0]), "r"(a[1]), "r"(a[2]), "r"(a[3]), "r"(b0), "r"(b1));
}

#define CLUSTER_ARRIVE() asm volatile("barrier.cluster.arrive.aligned;" ::: "memory")
#define CLUSTER_WAIT()   asm volatile("barrier.cluster.wait.aligned;"   ::: "memory")

__global__ void init_out_kernel(float* __restrict__ out, const float* __restrict__ b_out) {
    int i = blockIdx.x * blockDim.x + threadIdx.x;
    if (i < BB * TT * PP) out[i] = b_out[i & (PP - 1)];
}

// split X into interleaved {hi, lo} word layout: element w of (b,t) holds k-pair at
// d0 = (w>>3)*16 + ((w&7)>>1)*2 + (w&1)*8
__global__ void xsplit_kernel(const float* __restrict__ X) {
    int i = blockIdx.x * blockDim.x + threadIdx.x;
    if (i >= BB * TT * 16) return;
    int w = i & 15;
    int bt = i >> 4;              // b*TT + t
    int d0 = ((w >> 3) * 16) + (((w & 7) >> 1) * 2) + ((w & 1) * 8);
    float v0 = X[(size_t)bt * PP + d0];
    float v1 = X[(size_t)bt * PP + d0 + 1];
    __nv_bfloat16 h0 = __float2bfloat16(v0);
    __nv_bfloat16 h1 = __float2bfloat16(v1);
    float l0 = v0 - __bfloat162float(h0);
    float l1 = v1 - __bfloat162float(h1);
    uint32_t hiw = (uint32_t)__bfloat16_as_ushort(h0) | ((uint32_t)__bfloat16_as_ushort(h1) << 16);
    uint32_t low = pack_bf2(l0, l1);
    Xp_g[i] = make_uint2(hiw, low);
}

extern __shared__ char smem_c[];

__global__ void __cluster_dims__(CHUNK, 1, 1) __launch_bounds__(NTHREADS, 1)
clstm_mma_kernel(const float* __restrict__ Wih,
                 const float* __restrict__ Whh,
                 const float* __restrict__ bih,
                 const float* __restrict__ bhh,
                 const float* __restrict__ Wout,
                 float* __restrict__ out)
{
    const int tid  = threadIdx.x;
    const int lane = tid & 31;
    const int wid  = tid >> 5;           // 8 warps
    const int r    = lane >> 2;          // fragment row group
    const int tg   = lane & 3;           // fragment thread-in-group

    uint32_t rank;
    asm("mov.u32 %0, %%cluster_ctarank;" : "=r"(rank));
    const int n  = blockIdx.x >> 2;      // network id
    const int j0 = (int)rank * 32;

    float* S = reinterpret_cast<float*>(smem_c + OFF_S);

    // ---- zero both B buffers (h region must start at 0) ----
    {
        uint4 z = make_uint4(0, 0, 0, 0);
        for (int i = tid; i < 2 * BBYTES / 16; i += NTHREADS)
            reinterpret_cast<uint4*>(smem_c + OFF_B0)[i] = z;
    }

    // ---- bias + wout ----
    for (int idx = tid; idx < 4 * 32; idx += NTHREADS) {
        int g = idx >> 5, jl = idx & 31;
        int row = n * 4 * HH + g * HH + j0 + jl;
        *reinterpret_cast<float*>(smem_c + OFF_BIAS + idx * 4) = bih[row] + bhh[row];
    }
    if (tid < 32) *reinterpret_cast<float*>(smem_c + OFF_WOUT + tid * 4) = Wout[n * HH + j0 + tid];

    // zero-loop / bias / wout writes must complete before X staging or bias reads
    __syncthreads();

    // ---- load A fragments (weights) into registers, hi/lo split ----
    // warp w covers gate-rows m = w*16 + {r, r+8}; gate g = w>>1, jl = m&31
    uint32_t Ahi[KTILES][4], Alo[KTILES][4];
    {
        const int g = wid >> 1;
        const int m0 = wid * 16 + r;
        const int m1 = m0 + 8;
        const int jl0 = m0 & 31, jl1 = m1 & 31;
        const size_t grow0 = (size_t)(n * 4 * HH + g * HH + j0 + jl0);
        const size_t grow1 = (size_t)(n * 4 * HH + g * HH + j0 + jl1);
#pragma unroll
        for (int kt = 0; kt < KTILES; ++kt) {
#pragma unroll
            for (int e = 0; e < 4; ++e) {
                // e: 0 -> (m0, k0), 1 -> (m1, k0), 2 -> (m0, k0+8), 3 -> (m1, k0+8)
                size_t grow = (e & 1) ? grow1 : grow0;
                int k = kt * 16 + tg * 2 + ((e >> 1) * 8);
                float v0, v1;
                if (k < PP) {
                    v0 = Wih[grow * PP + k];
                    v1 = Wih[grow * PP + k + 1];
                } else {
                    v0 = Whh[grow * HH + (k - PP)];
                    v1 = Whh[grow * HH + (k - PP) + 1];
                }
                __nv_bfloat16 h0 = __float2bfloat16(v0);
                __nv_bfloat16 h1 = __float2bfloat16(v1);
                Ahi[kt][e] = (uint32_t)__bfloat16_as_ushort(h0) | ((uint32_t)__bfloat16_as_ushort(h1) << 16);
                Alo[kt][e] = pack_bf2(v0 - __bfloat162float(h0), v1 - __bfloat162float(h1));
            }
        }
    }

    // ---- stage X(t=0) into buffer 0 (after the sync: region is stably zeroed) ----
    const int xb  = tid >> 3;
    const int xwp = (tid & 7) * 2;        // element index (even)
    {
        uint4 v = *reinterpret_cast<const uint4*>(&Xp_g[((size_t)xb * TT + 0) * 16 + xwp]);
        *reinterpret_cast<uint4*>(smem_c + OFF_B0 + xb * ROWB + xwp * 8) = v;
    }

    // per-thread epilogue constants (post-barrier: values are valid)
    const float biasI = *reinterpret_cast<float*>(smem_c + OFF_BIAS + (0 * 32 + lane) * 4);
    const float biasF = *reinterpret_cast<float*>(smem_c + OFF_BIAS + (1 * 32 + lane) * 4);
    const float biasG = *reinterpret_cast<float*>(smem_c + OFF_BIAS + (2 * 32 + lane) * 4);
    const float biasO = *reinterpret_cast<float*>(smem_c + OFF_BIAS + (3 * 32 + lane) * 4);
    const float wout  = *reinterpret_cast<float*>(smem_c + OFF_WOUT + lane * 4);

    // this lane-pair's h-write ELEMENT offset (even k of the pair): khe = 32 + j0 + (lane & ~1)
    const int khe = PP + j0 + (lane & ~1);
    const uint32_t hoff8 = (uint32_t)((khe >> 4) * 8 + ((khe >> 1) & 3) * 2 + ((khe >> 3) & 1)) * 8;

    // smem base + peer bases
    uint32_t sbase;
    asm("{ .reg .u64 t0; cvta.to.shared.u64 t0, %1; cvt.u32.u64 %0, t0; }" : "=r"(sbase) : "l"(smem_c));
    uint32_t peer_base[CHUNK];
#pragma unroll
    for (int rr = 0; rr < CHUNK; ++rr)
        asm("mapa.shared::cluster.u32 %0, %1, %2;" : "=r"(peer_base[rr]) : "r"(sbase), "r"(rr));

    float c[4] = {0.0f, 0.0f, 0.0f, 0.0f};
    int buf = 0;

    // init done: release local init stores to the cluster (arrive #1)
    CLUSTER_ARRIVE();

    for (int t = 0; t < TT; ++t) {
        // prefetch X(t+1) from global BEFORE the wait — latency hidden by barrier+MMA
        int tn = (t + 1 < TT) ? (t + 1) : t;
        uint4 pv = *reinterpret_cast<const uint4*>(&Xp_g[((size_t)xb * TT + tn) * 16 + xwp]);

        // wait: all CTAs published h(t) + X(t) stores (arrive #(t+1))
        CLUSTER_WAIT();

        const char* bufp = smem_c + OFF_B0 + buf * BBYTES;

        // ---- split-GEMM: acc = A_hi*B_hi + A_hi*B_lo + A_lo*B_hi ----
        float acc[4][4];
#pragma unroll
        for (int nt = 0; nt < 4; ++nt)
#pragma unroll
            for (int e = 0; e < 4; ++e) acc[nt][e] = 0.0f;

#pragma unroll
        for (int kt = 0; kt < KTILES; ++kt) {
            uint4 bv[4];
#pragma unroll
            for (int nt = 0; nt < 4; ++nt) {
                uint32_t off = (uint32_t)(nt * 8 + r) * ROWB + (uint32_t)(kt * 8 + tg * 2) * 8;
                bv[nt] = *reinterpret_cast<const uint4*>(bufp + off);
            }
#pragma unroll
            for (int nt = 0; nt < 4; ++nt) mma16816(acc[nt], Ahi[kt], bv[nt].x, bv[nt].z);
#pragma unroll
            for (int nt = 0; nt < 4; ++nt) mma16816(acc[nt], Ahi[kt], bv[nt].y, bv[nt].w);
#pragma unroll
            for (int nt = 0; nt < 4; ++nt) mma16816(acc[nt], Alo[kt], bv[nt].x, bv[nt].z);
        }

        // ---- stage D -> S[g][jl][34 b] ----
        {
            const int g = wid >> 1;
            const int jlb = (wid & 1) * 16 + r;
#pragma unroll
            for (int nt = 0; nt < 4; ++nt) {
                int bcol = nt * 8 + tg * 2;
                *reinterpret_cast<float2*>(&S[(g * 32 + jlb) * S_PAD + bcol]) =
                    make_float2(acc[nt][0], acc[nt][1]);
                *reinterpret_cast<float2*>(&S[(g * 32 + jlb + 8) * S_PAD + bcol]) =
                    make_float2(acc[nt][2], acc[nt][3]);
            }
        }
        __syncthreads();

        const uint32_t offB_next = (uint32_t)(OFF_B0 + (buf ^ 1) * BBYTES);

        // ---- epilogue: activations + state + h broadcast ----
        float pout[4];
#pragma unroll
        for (int i = 0; i < 4; ++i) {
            int b = wid * 4 + i;
            float gi = S[(0 * 32 + lane) * S_PAD + b] + biasI;
            float gf = S[(1 * 32 + lane) * S_PAD + b] + biasF;
            float gg = S[(2 * 32 + lane) * S_PAD + b] + biasG;
            float go = S[(3 * 32 + lane) * S_PAD + b] + biasO;
            float ii = sigf(gi);
            float ff = sigf(gf);
            float g2 = tanha(gg);
            float oo = sigf(go);
            float cc = fmaf(ff, c[i], ii * g2);
            c[i] = cc;
            float h = oo * tanha(cc);

            __nv_bfloat16 hhb = __float2bfloat16(h);
            float rem = h - __bfloat162float(hhb);
            uint32_t vh = (uint32_t)__bfloat16_as_ushort(hhb);
            uint32_t vl = (uint32_t)__bfloat16_as_ushort(__float2bfloat16(rem));

            // pair up the two bf16 halves of each 32-bit word inside the warp
            uint32_t vhp = __shfl_down_sync(0xffffffffu, vh, 1);
            uint32_t vlp = __shfl_down_sync(0xffffffffu, vl, 1);
            if (!(lane & 1)) {
                uint32_t wordh = vh | (vhp << 16);
                uint32_t wordl = vl | (vlp << 16);
                uint32_t off = offB_next + (uint32_t)b * ROWB + hoff8;
                // own CTA via plain 64-bit shared store
                *reinterpret_cast<uint2*>(smem_c + off) = make_uint2(wordh, wordl);
                // peers via single 64-bit cluster stores
#pragma unroll
                for (int rr = 0; rr < CHUNK; ++rr) {
                    if (rr != (int)rank) {
                        asm volatile("st.shared::cluster.v2.u32 [%0], {%1, %2};"
                                     :: "r"(peer_base[rr] + off), "r"(wordh), "r"(wordl) : "memory");
                    }
                }
            }
            pout[i] = h * wout;
        }

        // ---- stage X(t+1) from prefetch regs into next buffer ----
        *reinterpret_cast<uint4*>(smem_c + offB_next + xb * ROWB + xwp * 8) = pv;

        // release this step's stores to the cluster; head work hides under peer skew
        CLUSTER_ARRIVE();

        // head: reduce this CTA's 32 j's, accumulate to out (off critical path)
#pragma unroll
        for (int i = 0; i < 4; ++i) {
#pragma unroll
            for (int m = 16; m > 0; m >>= 1)
                pout[i] += __shfl_xor_sync(0xffffffffu, pout[i], m);
        }
        if (lane == 0) {
#pragma unroll
            for (int i = 0; i < 4; ++i)
                atomicAdd(&out[((size_t)(wid * 4 + i) * TT + t) * PP + n], pout[i]);
        }

        buf ^= 1;
    }

    // consume the final arrive; no CTA exits while peer stores may be in flight
    CLUSTER_WAIT();
}

extern "C" void kernel_launch(void* const* d_in, const int* in_sizes, int n_in,
                              void* d_out, int out_size) {
    const float* X    = (const float*)d_in[0];
    const float* Wih  = (const float*)d_in[1];
    const float* Whh  = (const float*)d_in[2];
    const float* bih  = (const float*)d_in[3];
    const float* bhh  = (const float*)d_in[4];
    const float* Wout = (const float*)d_in[5];
    const float* bout = (const float*)d_in[6];
    float* out = (float*)d_out;

    cudaFuncSetAttribute(clstm_mma_kernel, cudaFuncAttributeMaxDynamicSharedMemorySize, SMEM_BYTES);

    init_out_kernel<<<(BB * TT * PP + 255) / 256, 256>>>(out, bout);
    xsplit_kernel<<<(BB * TT * 16 + 255) / 256, 256>>>(X);
    clstm_mma_kernel<<<PP * CHUNK, NTHREADS, SMEM_BYTES>>>(Wih, Whh, bih, bhh, Wout, out);
}

// round 10
// speedup vs baseline: 1.0292x; 1.0292x over previous
#include <cuda_runtime.h>
#include <cuda_bf16.h>
#include <cstdint>

#define PP 32      // num networks
#define HH 128     // hidden
#define BB 32      // batch
#define TT 256     // seq len
#define CHUNK 4    // CTAs per network (cluster size)
#define NTHREADS 256
#define KTILES 10  // K = 160 = 10 x 16

// B buffer: per n (batch), PADW words (u32 = packed bf16 k-pair), conflict-free
#define PADW 88
#define BBYTES (32 * PADW * 4)          // 11264 per buffer

// smem byte offsets
#define OFF_BIAS 0                       // 4*32 f32
#define OFF_WOUT 512                     // 32 f32
#define OFF_MB   640                     // 2 mbarriers (8B each)
#define OFF_B0   1024                    // 4 buffers: buf0_hi, buf0_lo, buf1_hi, buf1_lo
#define OFF_S    (1024 + 4 * BBYTES)     // D staging: [4 g][32 jl][34 b] f32
#define S_PAD    34
#define SMEM_BYTES (OFF_S + 4 * 32 * S_PAD * 4)   // 63488

// packed X scratch: [b][t][16 words] for k<32 region, hi and lo
__device__ uint32_t Xp_hi_g[BB * TT * 16];
__device__ uint32_t Xp_lo_g[BB * TT * 16];

__device__ __forceinline__ float tanha(float x) {
    float y; asm("tanh.approx.f32 %0, %1;" : "=f"(y) : "f"(x)); return y;
}
__device__ __forceinline__ float sigf(float x) {
    return fmaf(0.5f, tanha(0.5f * x), 0.5f);
}

__device__ __forceinline__ uint32_t pack_bf2(float lo_k, float hi_k) {
    unsigned short a = __bfloat16_as_ushort(__float2bfloat16(lo_k));
    unsigned short b = __bfloat16_as_ushort(__float2bfloat16(hi_k));
    return (uint32_t)a | ((uint32_t)b << 16);
}

__device__ __forceinline__ void mma16816(float* d, const uint32_t* a, uint32_t b0, uint32_t b1) {
    asm volatile(
        "mma.sync.aligned.m16n8k16.row.col.f32.bf16.bf16.f32 "
        "{%0,%1,%2,%3}, {%4,%5,%6,%7}, {%8,%9}, {%0,%1,%2,%3};"
        : "+f"(d[0]), "+f"(d[1]), "+f"(d[2]), "+f"(d[3])
        : "r"(a[0]), "r"(a[1]), "r"(a[2]), "r"(a[3]), "r"(b0), "r"(b1));
}

#define CLUSTER_BAR() do { \
    asm volatile("barrier.cluster.arrive.aligned;" ::: "memory"); \
    asm volatile("barrier.cluster.wait.aligned;"   ::: "memory"); } while (0)

// spin on local mbarrier with cluster-scope acquire
#define MBAR_WAIT_CL(addr, par) do { \
    uint32_t _done; \
    do { \
        asm volatile("{\n\t.reg .pred p;\n\t" \
            "mbarrier.try_wait.parity.acquire.cluster.shared::cta.b64 p, [%1], %2, 0x989680;\n\t" \
            "selp.b32 %0, 1, 0, p;\n\t}" \
            : "=r"(_done) : "r"(addr), "r"(par) : "memory"); \
    } while (!_done); \
} while (0)

__global__ void init_out_kernel(float* __restrict__ out, const float* __restrict__ b_out) {
    int i = blockIdx.x * blockDim.x + threadIdx.x;
    if (i < BB * TT * PP) out[i] = b_out[i & (PP - 1)];
}

// split X into packed hi/lo bf16 word layout: word w of n holds k-pair at
// d0 = (w>>3)*16 + ((w&7)>>1)*2 + (w&1)*8
__global__ void xsplit_kernel(const float* __restrict__ X) {
    int i = blockIdx.x * blockDim.x + threadIdx.x;
    if (i >= BB * TT * 16) return;
    int w = i & 15;
    int bt = i >> 4;              // b*TT + t
    int d0 = ((w >> 3) * 16) + (((w & 7) >> 1) * 2) + ((w & 1) * 8);
    float v0 = X[(size_t)bt * PP + d0];
    float v1 = X[(size_t)bt * PP + d0 + 1];
    __nv_bfloat16 h0 = __float2bfloat16(v0);
    __nv_bfloat16 h1 = __float2bfloat16(v1);
    float l0 = v0 - __bfloat162float(h0);
    float l1 = v1 - __bfloat162float(h1);
    Xp_hi_g[i] = (uint32_t)__bfloat16_as_ushort(h0) | ((uint32_t)__bfloat16_as_ushort(h1) << 16);
    Xp_lo_g[i] = pack_bf2(l0, l1);
}

extern __shared__ char smem_c[];

__global__ void __cluster_dims__(CHUNK, 1, 1) __launch_bounds__(NTHREADS, 1)
clstm_mma_kernel(const float* __restrict__ Wih,
                 const float* __restrict__ Whh,
                 const float* __restrict__ bih,
                 const float* __restrict__ bhh,
                 const float* __restrict__ Wout,
                 float* __restrict__ out)
{
    const int tid  = threadIdx.x;
    const int lane = tid & 31;
    const int wid  = tid >> 5;           // 8 warps
    const int r    = lane >> 2;          // fragment row group
    const int tg   = lane & 3;           // fragment thread-in-group

    uint32_t rank;
    asm("mov.u32 %0, %%cluster_ctarank;" : "=r"(rank));
    const int n  = blockIdx.x >> 2;      // network id
    const int j0 = (int)rank * 32;

    float* S = reinterpret_cast<float*>(smem_c + OFF_S);

    // smem base + peer bases
    uint32_t sbase;
    asm("{ .reg .u64 t0; cvta.to.shared.u64 t0, %1; cvt.u32.u64 %0, t0; }" : "=r"(sbase) : "l"(smem_c));
    uint32_t peer_base[CHUNK];
#pragma unroll
    for (int rr = 0; rr < CHUNK; ++rr)
        asm("mapa.shared::cluster.u32 %0, %1, %2;" : "=r"(peer_base[rr]) : "r"(sbase), "r"(rr));

    // ---- zero all B buffers (h region must start at 0) ----
    {
        uint4 z = make_uint4(0, 0, 0, 0);
        for (int i = tid; i < 4 * BBYTES / 16; i += NTHREADS)
            reinterpret_cast<uint4*>(smem_c + OFF_B0)[i] = z;
    }

    // ---- bias + wout ----
    for (int idx = tid; idx < 4 * 32; idx += NTHREADS) {
        int g = idx >> 5, jl = idx & 31;
        int row = n * 4 * HH + g * HH + j0 + jl;
        *reinterpret_cast<float*>(smem_c + OFF_BIAS + idx * 4) = bih[row] + bhh[row];
    }
    if (tid < 32) *reinterpret_cast<float*>(smem_c + OFF_WOUT + tid * 4) = Wout[n * HH + j0 + tid];

    // ---- init step mbarriers (count = CHUNK arrivals per phase) ----
    if (tid == 0) {
        asm volatile("mbarrier.init.shared.b64 [%0], %1;" :: "r"(sbase + OFF_MB + 0), "r"(CHUNK) : "memory");
        asm volatile("mbarrier.init.shared.b64 [%0], %1;" :: "r"(sbase + OFF_MB + 8), "r"(CHUNK) : "memory");
    }

    // zero-loop / bias / wout / mbarrier writes must complete before X staging or reads
    __syncthreads();

    // ---- load A fragments (weights) into registers, hi/lo split ----
    // warp w covers gate-rows m = w*16 + {r, r+8}; gate g = w>>1, jl = m&31
    uint32_t Ahi[KTILES][4], Alo[KTILES][4];
    {
        const int g = wid >> 1;
        const int m0 = wid * 16 + r;
        const int m1 = m0 + 8;
        const int jl0 = m0 & 31, jl1 = m1 & 31;
        const size_t grow0 = (size_t)(n * 4 * HH + g * HH + j0 + jl0);
        const size_t grow1 = (size_t)(n * 4 * HH + g * HH + j0 + jl1);
#pragma unroll
        for (int kt = 0; kt < KTILES; ++kt) {
#pragma unroll
            for (int e = 0; e < 4; ++e) {
                // e: 0 -> (m0, k0), 1 -> (m1, k0), 2 -> (m0, k0+8), 3 -> (m1, k0+8)
                size_t grow = (e & 1) ? grow1 : grow0;
                int k = kt * 16 + tg * 2 + ((e >> 1) * 8);
                float v0, v1;
                if (k < PP) {
                    v0 = Wih[grow * PP + k];
                    v1 = Wih[grow * PP + k + 1];
                } else {
                    v0 = Whh[grow * HH + (k - PP)];
                    v1 = Whh[grow * HH + (k - PP) + 1];
                }
                __nv_bfloat16 h0 = __float2bfloat16(v0);
                __nv_bfloat16 h1 = __float2bfloat16(v1);
                Ahi[kt][e] = (uint32_t)__bfloat16_as_ushort(h0) | ((uint32_t)__bfloat16_as_ushort(h1) << 16);
                Alo[kt][e] = pack_bf2(v0 - __bfloat162float(h0), v1 - __bfloat162float(h1));
            }
        }
    }

    // ---- stage X(t=0) into buffer 0 (after the sync: region is stably zeroed) ----
    const int xb  = tid >> 3;
    const int xwp = (tid & 7) * 2;
    {
        uint2 vh = *reinterpret_cast<const uint2*>(&Xp_hi_g[((size_t)xb * TT + 0) * 16 + xwp]);
        uint2 vl = *reinterpret_cast<const uint2*>(&Xp_lo_g[((size_t)xb * TT + 0) * 16 + xwp]);
        *reinterpret_cast<uint2*>(smem_c + OFF_B0 + (xb * PADW + xwp) * 4) = vh;
        *reinterpret_cast<uint2*>(smem_c + OFF_B0 + BBYTES + (xb * PADW + xwp) * 4) = vl;
    }

    // per-thread epilogue constants (post-barrier: values are valid)
    const float biasI = *reinterpret_cast<float*>(smem_c + OFF_BIAS + (0 * 32 + lane) * 4);
    const float biasF = *reinterpret_cast<float*>(smem_c + OFF_BIAS + (1 * 32 + lane) * 4);
    const float biasG = *reinterpret_cast<float*>(smem_c + OFF_BIAS + (2 * 32 + lane) * 4);
    const float biasO = *reinterpret_cast<float*>(smem_c + OFF_BIAS + (3 * 32 + lane) * 4);
    const float wout  = *reinterpret_cast<float*>(smem_c + OFF_WOUT + lane * 4);

    // this lane-pair's h-write WORD offset (even k of the pair): khe = 32 + j0 + (lane & ~1)
    const int khe = PP + j0 + (lane & ~1);
    const uint32_t hwrd4 = (uint32_t)((khe >> 4) * 8 + ((khe >> 1) & 3) * 2 + ((khe >> 3) & 1)) * 4;

    float c[4] = {0.0f, 0.0f, 0.0f, 0.0f};
    int buf = 0;

    // one-time full cluster barrier: all CTAs' zeroing / X(0) / mbarrier inits visible
    __syncthreads();
    CLUSTER_BAR();

    // pre-arrive for step 0 (each CTA arrives on every cluster CTA's mb[0])
    if (tid < CHUNK) {
        asm volatile("mbarrier.arrive.release.cluster.shared::cluster.b64 _, [%0];"
                     :: "r"(peer_base[tid] + OFF_MB + 0) : "memory");
    }

    for (int t = 0; t < TT; ++t) {
        // prefetch X(t+1) from global BEFORE the wait — latency hidden by barrier+MMA
        int tn = (t + 1 < TT) ? (t + 1) : t;
        uint2 pvh = *reinterpret_cast<const uint2*>(&Xp_hi_g[((size_t)xb * TT + tn) * 16 + xwp]);
        uint2 pvl = *reinterpret_cast<const uint2*>(&Xp_lo_g[((size_t)xb * TT + tn) * 16 + xwp]);

        // wait: all 4 CTAs published h(t) + X(t) stores into our buffer
        MBAR_WAIT_CL(sbase + OFF_MB + (uint32_t)(t & 1) * 8, (t >> 1) & 1);

        const char* bufhi = smem_c + OFF_B0 + buf * 2 * BBYTES;
        const char* buflo = bufhi + BBYTES;

        // ---- split-GEMM: acc = A_hi*B_hi + A_hi*B_lo + A_lo*B_hi ----
        float acc[4][4];
#pragma unroll
        for (int nt = 0; nt < 4; ++nt)
#pragma unroll
            for (int e = 0; e < 4; ++e) acc[nt][e] = 0.0f;

#pragma unroll
        for (int kt = 0; kt < KTILES; ++kt) {
            uint2 bh[4], bl[4];
#pragma unroll
            for (int nt = 0; nt < 4; ++nt) {
                uint32_t off = ((nt * 8 + r) * PADW + kt * 8 + tg * 2) * 4;
                bh[nt] = *reinterpret_cast<const uint2*>(bufhi + off);
                bl[nt] = *reinterpret_cast<const uint2*>(buflo + off);
            }
#pragma unroll
            for (int nt = 0; nt < 4; ++nt) mma16816(acc[nt], Ahi[kt], bh[nt].x, bh[nt].y);
#pragma unroll
            for (int nt = 0; nt < 4; ++nt) mma16816(acc[nt], Ahi[kt], bl[nt].x, bl[nt].y);
#pragma unroll
            for (int nt = 0; nt < 4; ++nt) mma16816(acc[nt], Alo[kt], bh[nt].x, bh[nt].y);
        }

        // ---- stage D -> S[g][jl][34 b] ----
        {
            const int g = wid >> 1;
            const int jlb = (wid & 1) * 16 + r;
#pragma unroll
            for (int nt = 0; nt < 4; ++nt) {
                int bcol = nt * 8 + tg * 2;
                *reinterpret_cast<float2*>(&S[(g * 32 + jlb) * S_PAD + bcol]) =
                    make_float2(acc[nt][0], acc[nt][1]);
                *reinterpret_cast<float2*>(&S[(g * 32 + jlb + 8) * S_PAD + bcol]) =
                    make_float2(acc[nt][2], acc[nt][3]);
            }
        }
        __syncthreads();

        const uint32_t offB_next = (uint32_t)(OFF_B0 + (buf ^ 1) * 2 * BBYTES);

        // ---- epilogue: activations + state + h broadcast ----
        float pout[4];
#pragma unroll
        for (int i = 0; i < 4; ++i) {
            int b = wid * 4 + i;
            float gi = S[(0 * 32 + lane) * S_PAD + b] + biasI;
            float gf = S[(1 * 32 + lane) * S_PAD + b] + biasF;
            float gg = S[(2 * 32 + lane) * S_PAD + b] + biasG;
            float go = S[(3 * 32 + lane) * S_PAD + b] + biasO;
            float ii = sigf(gi);
            float ff = sigf(gf);
            float g2 = tanha(gg);
            float oo = sigf(go);
            float cc = fmaf(ff, c[i], ii * g2);
            c[i] = cc;
            float h = oo * tanha(cc);

            __nv_bfloat16 hhb = __float2bfloat16(h);
            float rem = h - __bfloat162float(hhb);
            uint32_t vh = (uint32_t)__bfloat16_as_ushort(hhb);
            uint32_t vl = (uint32_t)__bfloat16_as_ushort(__float2bfloat16(rem));

            // pair up the two bf16 halves of each 32-bit B-word inside the warp
            uint32_t vhp = __shfl_down_sync(0xffffffffu, vh, 1);
            uint32_t vlp = __shfl_down_sync(0xffffffffu, vl, 1);
            if (!(lane & 1)) {
                uint32_t wordh = vh | (vhp << 16);
                uint32_t wordl = vl | (vlp << 16);
                uint32_t oh = offB_next + (uint32_t)b * (PADW * 4) + hwrd4;
                uint32_t ol = oh + BBYTES;
                // own CTA via plain shared store
                *reinterpret_cast<uint32_t*>(smem_c + oh) = wordh;
                *reinterpret_cast<uint32_t*>(smem_c + ol) = wordl;
                // peers via full-word cluster stores
#pragma unroll
                for (int rr = 0; rr < CHUNK; ++rr) {
                    if (rr != (int)rank) {
                        asm volatile("st.shared::cluster.u32 [%0], %1;" :: "r"(peer_base[rr] + oh), "r"(wordh) : "memory");
                        asm volatile("st.shared::cluster.u32 [%0], %1;" :: "r"(peer_base[rr] + ol), "r"(wordl) : "memory");
                    }
                }
            }
            pout[i] = h * wout;
        }

        // ---- stage X(t+1) from prefetch regs into next buffer ----
        *reinterpret_cast<uint2*>(smem_c + offB_next + (xb * PADW + xwp) * 4) = pvh;
        *reinterpret_cast<uint2*>(smem_c + offB_next + BBYTES + (xb * PADW + xwp) * 4) = pvl;

        // all threads' stores done -> publish via release-arrive to every CTA's mb[(t+1)&1]
        __syncthreads();
        if (tid < CHUNK) {
            asm volatile("mbarrier.arrive.release.cluster.shared::cluster.b64 _, [%0];"
                         :: "r"(peer_base[tid] + OFF_MB + (uint32_t)((t + 1) & 1) * 8) : "memory");
        }

        // head: reduce this CTA's 32 j's, accumulate to out (off critical path)
#pragma unroll
        for (int i = 0; i < 4; ++i) {
#pragma unroll
            for (int m = 16; m > 0; m >>= 1)
                pout[i] += __shfl_xor_sync(0xffffffffu, pout[i], m);
        }
        if (lane == 0) {
#pragma unroll
            for (int i = 0; i < 4; ++i)
                atomicAdd(&out[((size_t)(wid * 4 + i) * TT + t) * PP + n], pout[i]);
        }

        buf ^= 1;
    }

    // no CTA exits while peer stores/arrives may be in flight
    CLUSTER_BAR();
}

extern "C" void kernel_launch(void* const* d_in, const int* in_sizes, int n_in,
                              void* d_out, int out_size) {
    const float* X    = (const float*)d_in[0];
    const float* Wih  = (const float*)d_in[1];
    const float* Whh  = (const float*)d_in[2];
    const float* bih  = (const float*)d_in[3];
    const float* bhh  = (const float*)d_in[4];
    const float* Wout = (const float*)d_in[5];
    const float* bout = (const float*)d_in[6];
    float* out = (float*)d_out;

    cudaFuncSetAttribute(clstm_mma_kernel, cudaFuncAttributeMaxDynamicSharedMemorySize, SMEM_BYTES);

    init_out_kernel<<<(BB * TT * PP + 255) / 256, 256>>>(out, bout);
    xsplit_kernel<<<(BB * TT * 16 + 255) / 256, 256>>>(X);
    clstm_mma_kernel<<<PP * CHUNK, NTHREADS, SMEM_BYTES>>>(Wih, Whh, bih, bhh, Wout, out);
}